// round 8
// baseline (speedup 1.0000x reference)
#include <cuda_runtime.h>
#include <cuda_fp16.h>
#include <stdint.h>

// SNU on GB300 (base sm_103 ISA — mma.sync HMMA path):
//   out[b,h,t] = spike recurrence over xw[t,b,h] = sum_i x[b,i,t]*W[i,h]
//   B=128, I=512, H=512, T=512, DECAY=0.8
//
// Phase 1: transpose+split x -> fp16 pair (a0,a1) [b][t][i]; W -> (b0,b1) [h][i]
// Phase 2: HMMA GEMM, K=3*512 segments (a0b0, a0b1, a1b0) -> g_xw fp32
//          v2: 64x64 warp tiles (HMMA:LDSM ratio 2x), 5-stage cp.async pipeline
// Phase 3: recurrence v2: double-buffered smem staging of xw chunks

typedef unsigned long long ull;

__device__ float  g_xw[33554432];                 // 65536 x 512 fp32
__device__ __half g_a0[33554432], g_a1[33554432];
__device__ __half g_b0[262144],  g_b1[262144];

// ---------------------------------------------------------------- helpers ---
__device__ __forceinline__ uint32_t smem_u32(const void* p) {
    uint32_t a;
    asm("{ .reg .u64 t; cvta.to.shared.u64 t, %1; cvt.u32.u64 %0, t; }"
        : "=r"(a) : "l"(p));
    return a;
}
__device__ __forceinline__ void cp16(uint32_t dst, const void* src) {
    asm volatile("cp.async.cg.shared.global [%0], [%1], 16;"
                 :: "r"(dst), "l"(src) : "memory");
}
__device__ __forceinline__ void ldsm4(uint32_t a, uint32_t& r0, uint32_t& r1,
                                      uint32_t& r2, uint32_t& r3) {
    asm volatile("ldmatrix.sync.aligned.m8n8.x4.shared.b16 {%0,%1,%2,%3}, [%4];"
                 : "=r"(r0), "=r"(r1), "=r"(r2), "=r"(r3) : "r"(a));
}
__device__ __forceinline__ void mma16816(float* d, const uint32_t* a,
                                         uint32_t b0, uint32_t b1) {
    asm volatile(
        "mma.sync.aligned.m16n8k16.row.col.f32.f16.f16.f32 "
        "{%0,%1,%2,%3}, {%4,%5,%6,%7}, {%8,%9}, {%0,%1,%2,%3};"
        : "+f"(d[0]), "+f"(d[1]), "+f"(d[2]), "+f"(d[3])
        : "r"(a[0]), "r"(a[1]), "r"(a[2]), "r"(a[3]), "r"(b0), "r"(b1));
}

// ------------------------------------------------------------ convert pass ---
__device__ __forceinline__ void trans_split2(
    const float* __restrict__ src, size_t src_off, size_t dst_off,
    int r0, int c0, __half* __restrict__ d0, __half* __restrict__ d1,
    float smtile[64][65])
{
    const float* sp = src + src_off + (size_t)r0 * 512 + c0;
    for (int e = threadIdx.x; e < 1024; e += 256) {
        int r = e >> 4, c = (e & 15) << 2;
        float4 v = *(const float4*)(sp + (size_t)r * 512 + c);
        smtile[r][c] = v.x; smtile[r][c + 1] = v.y;
        smtile[r][c + 2] = v.z; smtile[r][c + 3] = v.w;
    }
    __syncthreads();
    size_t ob = dst_off + (size_t)c0 * 512 + r0;
    for (int e = threadIdx.x; e < 1024; e += 256) {
        int r = e >> 4, c = (e & 15) << 2;
        union { __half h[4]; ull u; } p0, p1;
        #pragma unroll
        for (int q = 0; q < 4; q++) {
            float v = smtile[c + q][r];
            __half h0 = __float2half_rn(v);
            float rr = v - __half2float(h0);
            __half h1 = __float2half_rn(rr);
            p0.h[q] = h0; p1.h[q] = h1;
        }
        size_t o = ob + (size_t)r * 512 + c;
        *(ull*)(d0 + o) = p0.u;
        *(ull*)(d1 + o) = p1.u;
    }
    __syncthreads();
}

__global__ __launch_bounds__(256) void convert_x_kernel(const float* __restrict__ x) {
    __shared__ float tile[64][65];
    size_t boff = (size_t)blockIdx.z * 262144;
    trans_split2(x, boff, boff, blockIdx.y * 64, blockIdx.x * 64, g_a0, g_a1, tile);
}
__global__ __launch_bounds__(256) void convert_w_kernel(const float* __restrict__ W) {
    __shared__ float tile[64][65];
    trans_split2(W, 0, 0, blockIdx.y * 64, blockIdx.x * 64, g_b0, g_b1, tile);
}

// --------------------------------------------------------------- GEMM pass ---
// CTA 128(M) x 128(N) x 32(K-chunk), 128 threads = 4 warps (2m x 2n),
// warp tile 64x64.  5-stage cp.async pipeline (4-chunk lookahead).
// Stage: A 128 rows x 40 halves (80B pitch, ldmatrix conflict-free) + B same.

#define STG_B   20480
#define BPITCH  40
#define NSTG    5

__global__ __launch_bounds__(128, 2) void gemm_hmma() {
    extern __shared__ __half smraw[];
    const uint32_t smb = smem_u32(smraw);

    const int tid  = threadIdx.x;
    const int n0   = blockIdx.x * 128;
    const int m0   = blockIdx.y * 128;
    const int wid  = tid >> 5, lane = tid & 31;
    const int mw   = (wid >> 1) * 64;
    const int nw   = (wid & 1) * 64;

    float acc[4][8][4];
    #pragma unroll
    for (int i = 0; i < 4; i++)
        #pragma unroll
        for (int j = 0; j < 8; j++)
            #pragma unroll
            for (int q = 0; q < 4; q++) acc[i][j][q] = 0.0f;

    // loads: thread owns one 128-row; 4 cp16 for A + 4 for B per chunk
    // chunk c (0..47): K segment = c>>4, local k = (c&15)*32
    #define LOAD_CHUNK(c) do {                                                \
        int _seg  = (c) >> 4;                                                 \
        int _kloc = ((c) & 15) << 5;                                          \
        int _slot = (c) % NSTG;                                               \
        const __half* _ap = (_seg == 2) ? g_a1 : g_a0;                        \
        const __half* _bp = (_seg == 1) ? g_b1 : g_b0;                        \
        uint32_t _s = smb + _slot * STG_B + tid * (BPITCH * 2);               \
        const __half* _ag = _ap + (size_t)(m0 + tid) * 512 + _kloc;           \
        const __half* _bg = _bp + (size_t)(n0 + tid) * 512 + _kloc;           \
        cp16(_s,              _ag);      cp16(_s + 16,         _ag + 8);      \
        cp16(_s + 32,         _ag + 16); cp16(_s + 48,         _ag + 24);     \
        cp16(_s + 10240,      _bg);      cp16(_s + 10240 + 16, _bg + 8);      \
        cp16(_s + 10240 + 32, _bg + 16); cp16(_s + 10240 + 48, _bg + 24);     \
    } while (0)

    LOAD_CHUNK(0); asm volatile("cp.async.commit_group;" ::: "memory");
    LOAD_CHUNK(1); asm volatile("cp.async.commit_group;" ::: "memory");
    LOAD_CHUNK(2); asm volatile("cp.async.commit_group;" ::: "memory");
    LOAD_CHUNK(3); asm volatile("cp.async.commit_group;" ::: "memory");

    for (int i = 0; i < 48; i++) {
        asm volatile("cp.async.wait_group 3;" ::: "memory");
        __syncthreads();
        if (i + 4 < 48) LOAD_CHUNK(i + 4);
        asm volatile("cp.async.commit_group;" ::: "memory");

        const uint32_t base = smb + (i % NSTG) * STG_B;
        #pragma unroll
        for (int ks = 0; ks < 2; ks++) {
            const int col = ks * 16 + (lane >> 4) * 8;
            uint32_t ar[4][4], br[4][4];
            #pragma unroll
            for (int mi = 0; mi < 4; mi++) {
                int row = mw + mi * 16 + (lane & 15);
                ldsm4(base + (row * BPITCH + col) * 2,
                      ar[mi][0], ar[mi][1], ar[mi][2], ar[mi][3]);
            }
            #pragma unroll
            for (int nb = 0; nb < 4; nb++) {
                int row = nw + nb * 16 + (lane & 15);
                ldsm4(base + 10240 + (row * BPITCH + col) * 2,
                      br[nb][0], br[nb][1], br[nb][2], br[nb][3]);
            }
            #pragma unroll
            for (int mi = 0; mi < 4; mi++)
                #pragma unroll
                for (int nf = 0; nf < 8; nf++) {
                    int nb = nf >> 1, hh = nf & 1;
                    mma16816(acc[mi][nf], ar[mi], br[nb][hh], br[nb][hh + 2]);
                }
        }
    }

    // epilogue: frag map m = lane/4 [+8], n = 2*(lane%4) [+1]
    #pragma unroll
    for (int mi = 0; mi < 4; mi++) {
        int row = m0 + mw + mi * 16 + (lane >> 2);
        #pragma unroll
        for (int nf = 0; nf < 8; nf++) {
            int col = n0 + nw + nf * 8 + ((lane & 3) << 1);
            *(float2*)(g_xw + (size_t)row * 512 + col) =
                make_float2(acc[mi][nf][0], acc[mi][nf][1]);
            *(float2*)(g_xw + (size_t)(row + 8) * 512 + col) =
                make_float2(acc[mi][nf][2], acc[mi][nf][3]);
        }
    }
}

// ---------------------------------------------------------------- recurrence ---
// v2: double-buffered cp.async staging of 32-t chunks of xw (decouple the
// serial chain from DRAM latency).  Dynamic smem:
//   in[2][32][128] floats (32KB) + outbuf[128][33] (16.9KB)

__global__ __launch_bounds__(128) void recur_kernel(
    const float* __restrict__ bias, float* __restrict__ out)
{
    extern __shared__ float dyn[];
    float* smin = dyn;                               // [2][32*128]
    float (*buf)[33] = (float(*)[33])(dyn + 8192);   // [128][33]

    const int b  = blockIdx.x >> 2;
    const int h0 = (blockIdx.x & 3) * 128;
    const int h  = h0 + threadIdx.x;
    const int tid = threadIdx.x;

    const float bb = bias[h];
    float hs = 0.0f, y = 0.0f;

    const float* gx = g_xw + ((size_t)b * 512) * 512 + h0;   // + t*512 + hh
    float*       po = out + ((size_t)b * 512 + h0) * 512;

    const uint32_t smin_u = smem_u32(smin);
    const int lrow = tid >> 2;            // 0..31 (t within chunk)
    const int lq   = (tid & 3) * 32;      // 32-float quarter of the 128-h row

    // load chunk (32 t-rows x 128 floats) into buffer bsel
    #define RLOAD(tc0, bsel) do {                                             \
        const float* _src = gx + (size_t)((tc0) + lrow) * 512 + lq;           \
        uint32_t _dst = smin_u + (((bsel) * 4096 + lrow * 128 + lq) * 4);     \
        cp16(_dst,      _src);      cp16(_dst + 16, _src + 4);                \
        cp16(_dst + 32, _src + 8);  cp16(_dst + 48, _src + 12);               \
        cp16(_dst + 64, _src + 16); cp16(_dst + 80, _src + 20);               \
        cp16(_dst + 96, _src + 24); cp16(_dst + 112, _src + 28);              \
    } while (0)

    RLOAD(0, 0);
    asm volatile("cp.async.commit_group;" ::: "memory");

    for (int tc = 0; tc < 16; tc++) {
        if (tc < 15) {
            RLOAD((tc + 1) * 32, (tc + 1) & 1);
            asm volatile("cp.async.commit_group;" ::: "memory");
            asm volatile("cp.async.wait_group 1;" ::: "memory");
        } else {
            asm volatile("cp.async.wait_group 0;" ::: "memory");
        }
        __syncthreads();

        const float* cs = smin + (tc & 1) * 4096;
        #pragma unroll
        for (int j = 0; j < 32; j++) {
            float v = cs[j * 128 + tid];
            hs = fmaxf(v + 0.8f * hs * (1.0f - y), 0.0f);
            y  = (hs + bb > 0.0f) ? 1.0f : 0.0f;
            buf[tid][j] = y;
        }
        __syncthreads();
        const int r = tid >> 5;
        const int c = tid & 31;
        #pragma unroll
        for (int rr = 0; rr < 128; rr += 4)
            po[(size_t)(rr + r) * 512 + tc * 32 + c] = buf[rr + r][c];
        __syncthreads();
    }
}

// ------------------------------------------------------------------- launch ---
extern "C" void kernel_launch(void* const* d_in, const int* in_sizes, int n_in,
                              void* d_out, int out_size)
{
    const float* x = (const float*)d_in[0];   // (128, 512, 512)
    const float* W = (const float*)d_in[1];   // (512, 512)
    const float* b = (const float*)d_in[2];   // (1, 512)
    float* out = (float*)d_out;               // (128, 512, 512) float32

    cudaFuncSetAttribute(gemm_hmma,
                         cudaFuncAttributeMaxDynamicSharedMemorySize, NSTG * STG_B);
    cudaFuncSetAttribute(recur_kernel,
                         cudaFuncAttributeMaxDynamicSharedMemorySize, 49664);

    convert_x_kernel<<<dim3(8, 8, 128), 256>>>(x);
    convert_w_kernel<<<dim3(8, 8), 256>>>(W);
    gemm_hmma<<<dim3(4, 512), 128, NSTG * STG_B>>>();
    recur_kernel<<<512, 128, 49664>>>(b, out);
}

// round 9
// speedup vs baseline: 1.2298x; 1.2298x over previous
#include <cuda_runtime.h>
#include <cuda_fp16.h>
#include <stdint.h>

// SNU on GB300 (base sm_103 ISA — mma.sync HMMA path):
//   out[b,h,t] = spike recurrence over xw[t,b,h] = sum_i x[b,i,t]*W[i,h]
//   B=128, I=512, H=512, T=512, DECAY=0.8
//
// Phase 1: transpose+split x -> fp16 pair (a0,a1) [b][t][i]; W -> (b0,b1) [h][i]
// Phase 2: HMMA GEMM, K=3*512 segments (a0b0, a0b1, a1b0) -> g_xw fp32
//          (round-7 proven config: 256 thr, 32x64 warp tiles, 4-stage cp.async)
// Phase 3: recurrence v3: 3-buffer cp.async staging, lookahead 2

typedef unsigned long long ull;

__device__ float  g_xw[33554432];                 // 65536 x 512 fp32
__device__ __half g_a0[33554432], g_a1[33554432];
__device__ __half g_b0[262144],  g_b1[262144];

// ---------------------------------------------------------------- helpers ---
__device__ __forceinline__ uint32_t smem_u32(const void* p) {
    uint32_t a;
    asm("{ .reg .u64 t; cvta.to.shared.u64 t, %1; cvt.u32.u64 %0, t; }"
        : "=r"(a) : "l"(p));
    return a;
}
__device__ __forceinline__ void cp16(uint32_t dst, const void* src) {
    asm volatile("cp.async.cg.shared.global [%0], [%1], 16;"
                 :: "r"(dst), "l"(src) : "memory");
}
__device__ __forceinline__ void ldsm4(uint32_t a, uint32_t& r0, uint32_t& r1,
                                      uint32_t& r2, uint32_t& r3) {
    asm volatile("ldmatrix.sync.aligned.m8n8.x4.shared.b16 {%0,%1,%2,%3}, [%4];"
                 : "=r"(r0), "=r"(r1), "=r"(r2), "=r"(r3) : "r"(a));
}
__device__ __forceinline__ void mma16816(float* d, const uint32_t* a,
                                         uint32_t b0, uint32_t b1) {
    asm volatile(
        "mma.sync.aligned.m16n8k16.row.col.f32.f16.f16.f32 "
        "{%0,%1,%2,%3}, {%4,%5,%6,%7}, {%8,%9}, {%0,%1,%2,%3};"
        : "+f"(d[0]), "+f"(d[1]), "+f"(d[2]), "+f"(d[3])
        : "r"(a[0]), "r"(a[1]), "r"(a[2]), "r"(a[3]), "r"(b0), "r"(b1));
}

// ------------------------------------------------------------ convert pass ---
__device__ __forceinline__ void trans_split2(
    const float* __restrict__ src, size_t src_off, size_t dst_off,
    int r0, int c0, __half* __restrict__ d0, __half* __restrict__ d1,
    float smtile[64][65])
{
    const float* sp = src + src_off + (size_t)r0 * 512 + c0;
    for (int e = threadIdx.x; e < 1024; e += 256) {
        int r = e >> 4, c = (e & 15) << 2;
        float4 v = *(const float4*)(sp + (size_t)r * 512 + c);
        smtile[r][c] = v.x; smtile[r][c + 1] = v.y;
        smtile[r][c + 2] = v.z; smtile[r][c + 3] = v.w;
    }
    __syncthreads();
    size_t ob = dst_off + (size_t)c0 * 512 + r0;
    for (int e = threadIdx.x; e < 1024; e += 256) {
        int r = e >> 4, c = (e & 15) << 2;
        union { __half h[4]; ull u; } p0, p1;
        #pragma unroll
        for (int q = 0; q < 4; q++) {
            float v = smtile[c + q][r];
            __half h0 = __float2half_rn(v);
            float rr = v - __half2float(h0);
            __half h1 = __float2half_rn(rr);
            p0.h[q] = h0; p1.h[q] = h1;
        }
        size_t o = ob + (size_t)r * 512 + c;
        *(ull*)(d0 + o) = p0.u;
        *(ull*)(d1 + o) = p1.u;
    }
    __syncthreads();
}

__global__ __launch_bounds__(256) void convert_x_kernel(const float* __restrict__ x) {
    __shared__ float tile[64][65];
    size_t boff = (size_t)blockIdx.z * 262144;
    trans_split2(x, boff, boff, blockIdx.y * 64, blockIdx.x * 64, g_a0, g_a1, tile);
}
__global__ __launch_bounds__(256) void convert_w_kernel(const float* __restrict__ W) {
    __shared__ float tile[64][65];
    trans_split2(W, 0, 0, blockIdx.y * 64, blockIdx.x * 64, g_b0, g_b1, tile);
}

// --------------------------------------------------------------- GEMM pass ---
// Round-7 proven config.
// CTA tile 128(M) x 128(N) x 32(K-chunk). 256 threads = 8 warps (4m x 2n),
// warp tile 32x64. 4-stage cp.async pipeline.  Stage: A 128x40 halves
// (80B pitch, conflict-free ldmatrix) + B same = 20480 B.

#define STG_B   20480
#define BPITCH  40

__global__ __launch_bounds__(256, 2) void gemm_hmma() {
    extern __shared__ __half smraw[];
    const uint32_t smb = smem_u32(smraw);

    const int tid  = threadIdx.x;
    const int n0   = blockIdx.x * 128;
    const int m0   = blockIdx.y * 128;
    const int wid  = tid >> 5, lane = tid & 31;
    const int mw   = (wid >> 1) * 32;
    const int nw   = (wid & 1) * 64;

    float acc[2][8][4];
    #pragma unroll
    for (int i = 0; i < 2; i++)
        #pragma unroll
        for (int j = 0; j < 8; j++)
            #pragma unroll
            for (int q = 0; q < 4; q++) acc[i][j][q] = 0.0f;

    const int lrow = tid >> 1;          // 0..127
    const int lch  = (tid & 1) * 2;     // 16B-chunk index {0,2} within 64B row

    // chunk c (0..47): K segment = c>>4, local k = (c&15)*32
    #define LOAD_CHUNK(c, slot) do {                                          \
        int _seg  = (c) >> 4;                                                 \
        int _kloc = ((c) & 15) << 5;                                          \
        const __half* _ap = (_seg == 2) ? g_a1 : g_a0;                        \
        const __half* _bp = (_seg == 1) ? g_b1 : g_b0;                        \
        uint32_t _sA = smb + (slot) * STG_B + (lrow * BPITCH + lch * 8) * 2;  \
        const __half* _ag = _ap + (size_t)(m0 + lrow) * 512 + _kloc + lch * 8;\
        const __half* _bg = _bp + (size_t)(n0 + lrow) * 512 + _kloc + lch * 8;\
        cp16(_sA,          _ag);  cp16(_sA + 16,          _ag + 8);           \
        cp16(_sA + 10240,  _bg);  cp16(_sA + 10240 + 16,  _bg + 8);           \
    } while (0)

    LOAD_CHUNK(0, 0); asm volatile("cp.async.commit_group;" ::: "memory");
    LOAD_CHUNK(1, 1); asm volatile("cp.async.commit_group;" ::: "memory");
    LOAD_CHUNK(2, 2); asm volatile("cp.async.commit_group;" ::: "memory");

    for (int i = 0; i < 48; i++) {
        asm volatile("cp.async.wait_group 2;" ::: "memory");
        __syncthreads();
        if (i + 3 < 48) LOAD_CHUNK(i + 3, (i + 3) & 3);
        asm volatile("cp.async.commit_group;" ::: "memory");

        const uint32_t base = smb + (i & 3) * STG_B;
        #pragma unroll
        for (int ks = 0; ks < 2; ks++) {
            const int col = ks * 16 + (lane >> 4) * 8;
            uint32_t ar[2][4], br[4][4];
            #pragma unroll
            for (int mi = 0; mi < 2; mi++) {
                int row = mw + mi * 16 + (lane & 15);
                ldsm4(base + (row * BPITCH + col) * 2,
                      ar[mi][0], ar[mi][1], ar[mi][2], ar[mi][3]);
            }
            #pragma unroll
            for (int nb = 0; nb < 4; nb++) {
                int row = nw + nb * 16 + (lane & 15);
                ldsm4(base + 10240 + (row * BPITCH + col) * 2,
                      br[nb][0], br[nb][1], br[nb][2], br[nb][3]);
            }
            #pragma unroll
            for (int mi = 0; mi < 2; mi++)
                #pragma unroll
                for (int nf = 0; nf < 8; nf++) {
                    int nb = nf >> 1, hh = nf & 1;
                    mma16816(acc[mi][nf], ar[mi], br[nb][hh], br[nb][hh + 2]);
                }
        }
    }

    // epilogue: frag map m = lane/4 [+8], n = 2*(lane%4) [+1]
    #pragma unroll
    for (int mi = 0; mi < 2; mi++) {
        int row = m0 + mw + mi * 16 + (lane >> 2);
        #pragma unroll
        for (int nf = 0; nf < 8; nf++) {
            int col = n0 + nw + nf * 8 + ((lane & 3) << 1);
            *(float2*)(g_xw + (size_t)row * 512 + col) =
                make_float2(acc[mi][nf][0], acc[mi][nf][1]);
            *(float2*)(g_xw + (size_t)(row + 8) * 512 + col) =
                make_float2(acc[mi][nf][2], acc[mi][nf][3]);
        }
    }
}

// ---------------------------------------------------------------- recurrence ---
// v3: 3-buffer cp.async staging, lookahead 2 (32KB in flight per CTA).
// Dynamic smem: in[3][32][128] floats (48KB) + outbuf[128][33] (16.9KB) = 65.4KB

__global__ __launch_bounds__(128) void recur_kernel(
    const float* __restrict__ bias, float* __restrict__ out)
{
    extern __shared__ float dyn[];
    float* smin = dyn;                                // [3][32*128]
    float (*buf)[33] = (float(*)[33])(dyn + 12288);   // [128][33]

    const int b  = blockIdx.x >> 2;
    const int h0 = (blockIdx.x & 3) * 128;
    const int h  = h0 + threadIdx.x;
    const int tid = threadIdx.x;

    const float bb = bias[h];
    float hs = 0.0f, y = 0.0f;

    const float* gx = g_xw + ((size_t)b * 512) * 512 + h0;   // + t*512 + hh
    float*       po = out + ((size_t)b * 512 + h0) * 512;

    const uint32_t smin_u = smem_u32(smin);
    const int lrow = tid >> 2;            // 0..31 (t within chunk)
    const int lq   = (tid & 3) * 32;      // 32-float quarter of the 128-h row

    #define RLOAD(tc0, bsel) do {                                             \
        const float* _src = gx + (size_t)((tc0) + lrow) * 512 + lq;           \
        uint32_t _dst = smin_u + (((bsel) * 4096 + lrow * 128 + lq) * 4);     \
        cp16(_dst,      _src);      cp16(_dst + 16, _src + 4);                \
        cp16(_dst + 32, _src + 8);  cp16(_dst + 48, _src + 12);               \
        cp16(_dst + 64, _src + 16); cp16(_dst + 80, _src + 20);               \
        cp16(_dst + 96, _src + 24); cp16(_dst + 112, _src + 28);              \
    } while (0)

    RLOAD(0, 0);  asm volatile("cp.async.commit_group;" ::: "memory");
    RLOAD(32, 1); asm volatile("cp.async.commit_group;" ::: "memory");

    for (int tc = 0; tc < 16; tc++) {
        if (tc + 2 < 16) {
            RLOAD((tc + 2) * 32, (tc + 2) % 3);
            asm volatile("cp.async.commit_group;" ::: "memory");
            asm volatile("cp.async.wait_group 2;" ::: "memory");
        } else {
            asm volatile("cp.async.wait_group 0;" ::: "memory");
        }
        __syncthreads();

        const float* cs = smin + (tc % 3) * 4096;
        #pragma unroll
        for (int j = 0; j < 32; j++) {
            float v = cs[j * 128 + tid];
            hs = fmaxf(v + 0.8f * hs * (1.0f - y), 0.0f);
            y  = (hs + bb > 0.0f) ? 1.0f : 0.0f;
            buf[tid][j] = y;
        }
        __syncthreads();
        const int r = tid >> 5;
        const int c = tid & 31;
        #pragma unroll
        for (int rr = 0; rr < 128; rr += 4)
            po[(size_t)(rr + r) * 512 + tc * 32 + c] = buf[rr + r][c];
        __syncthreads();
    }
}

// ------------------------------------------------------------------- launch ---
extern "C" void kernel_launch(void* const* d_in, const int* in_sizes, int n_in,
                              void* d_out, int out_size)
{
    const float* x = (const float*)d_in[0];   // (128, 512, 512)
    const float* W = (const float*)d_in[1];   // (512, 512)
    const float* b = (const float*)d_in[2];   // (1, 512)
    float* out = (float*)d_out;               // (128, 512, 512) float32

    cudaFuncSetAttribute(gemm_hmma,
                         cudaFuncAttributeMaxDynamicSharedMemorySize, 4 * STG_B);
    cudaFuncSetAttribute(recur_kernel,
                         cudaFuncAttributeMaxDynamicSharedMemorySize, 66048);

    convert_x_kernel<<<dim3(8, 8, 128), 256>>>(x);
    convert_w_kernel<<<dim3(8, 8), 256>>>(W);
    gemm_hmma<<<dim3(4, 512), 256, 4 * STG_B>>>();
    recur_kernel<<<512, 128, 66048>>>(b, out);
}